// round 3
// baseline (speedup 1.0000x reference)
#include <cuda_runtime.h>
#include <math.h>

#define HID     2048
#define KVD     512
#define HEADS   16
#define GROUPS  4
#define HDIM    128
#define BATCH   2
#define SEQ     2048
#define MROWS   (BATCH*SEQ)   // 4096

// ---------------- scratch (no cudaMalloc allowed) ----------------
__device__ float g_Q[(size_t)MROWS * HID];   // 32 MB
__device__ float g_K[(size_t)MROWS * KVD];   //  8 MB
__device__ float g_V[(size_t)MROWS * KVD];   //  8 MB
__device__ float g_O[(size_t)MROWS * HID];   // 32 MB

// ================= GEMM: C[M,N] = A[M,K] @ W[K,N] + bias =================
// BM=BN=128, BK=8, 256 threads, 8x8 micro-tile (split 4+4 in each dim).
__global__ __launch_bounds__(256) void gemm_bias_kernel(
    const float* __restrict__ A, const float* __restrict__ W,
    const float* __restrict__ bias, float* __restrict__ C,
    int M, int N, int K)
{
    __shared__ float As[8][128];   // transposed A tile: As[k][m]
    __shared__ float Bs[8][128];   // Bs[k][n]

    const int tid = threadIdx.x;
    const int tx = tid & 15;       // 0..15 -> cols
    const int ty = tid >> 4;       // 0..15 -> rows
    const int bm = blockIdx.y * 128;
    const int bn = blockIdx.x * 128;

    float acc[8][8];
#pragma unroll
    for (int i = 0; i < 8; i++)
#pragma unroll
        for (int j = 0; j < 8; j++) acc[i][j] = 0.f;

    const int a_r = tid >> 1;          // 0..127
    const int a_c = (tid & 1) * 4;     // 0 or 4
    const int b_r = tid >> 5;          // 0..7
    const int b_c = (tid & 31) * 4;    // 0..124

    const float* Aptr = A + (size_t)(bm + a_r) * K + a_c;
    const float* Wptr = W + (size_t)b_r * N + bn + b_c;

    for (int k0 = 0; k0 < K; k0 += 8) {
        float4 av = *(const float4*)(Aptr);
        float4 bv = *(const float4*)(Wptr);
        __syncthreads();
        As[a_c + 0][a_r] = av.x;
        As[a_c + 1][a_r] = av.y;
        As[a_c + 2][a_r] = av.z;
        As[a_c + 3][a_r] = av.w;
        *(float4*)&Bs[b_r][b_c] = bv;
        __syncthreads();
        Aptr += 8;
        Wptr += (size_t)8 * N;

#pragma unroll
        for (int kk = 0; kk < 8; kk++) {
            float4 a0 = *(const float4*)&As[kk][ty * 4];
            float4 a1 = *(const float4*)&As[kk][64 + ty * 4];
            float4 b0 = *(const float4*)&Bs[kk][tx * 4];
            float4 b1 = *(const float4*)&Bs[kk][64 + tx * 4];
            float ar[8] = {a0.x, a0.y, a0.z, a0.w, a1.x, a1.y, a1.z, a1.w};
            float br[8] = {b0.x, b0.y, b0.z, b0.w, b1.x, b1.y, b1.z, b1.w};
#pragma unroll
            for (int i = 0; i < 8; i++)
#pragma unroll
                for (int j = 0; j < 8; j++)
                    acc[i][j] += ar[i] * br[j];
        }
    }

    // epilogue: add bias, vectorized store
    float4 bia0 = *(const float4*)&bias[bn + tx * 4];
    float4 bia1 = *(const float4*)&bias[bn + 64 + tx * 4];
#pragma unroll
    for (int i = 0; i < 8; i++) {
        int row = bm + ((i < 4) ? (ty * 4 + i) : (64 + ty * 4 + i - 4));
        float4 o0, o1;
        o0.x = acc[i][0] + bia0.x; o0.y = acc[i][1] + bia0.y;
        o0.z = acc[i][2] + bia0.z; o0.w = acc[i][3] + bia0.w;
        o1.x = acc[i][4] + bia1.x; o1.y = acc[i][5] + bia1.y;
        o1.z = acc[i][6] + bia1.z; o1.w = acc[i][7] + bia1.w;
        *(float4*)&C[(size_t)row * N + bn + tx * 4] = o0;
        *(float4*)&C[(size_t)row * N + bn + 64 + tx * 4] = o1;
    }
}

// ================= Flash-style attention =================
// Grid: (SEQ/64, HEADS, BATCH). 256 threads. 64-row Q tile, 64-key K/V tiles.
#define BQ 64
#define BK 64
#define RPAD 132   // padded row (128+4): strided column reads are 2-way, not 32-way
#define PPAD 68

#define QS_OFF 0
#define KS_OFF (BQ * RPAD)
#define VS_OFF (2 * BQ * RPAD)
#define PS_OFF (3 * BQ * RPAD)
#define MS_OFF (3 * BQ * RPAD + BQ * PPAD)
#define ATTN_SMEM_BYTES ((3 * BQ * RPAD + BQ * PPAD + BK) * 4)

__global__ __launch_bounds__(256) void attn_kernel(const int* __restrict__ mask)
{
    extern __shared__ float smem[];
    float (*Qs)[RPAD] = (float(*)[RPAD])(smem + QS_OFF);
    float (*Ks)[RPAD] = (float(*)[RPAD])(smem + KS_OFF);
    float (*Vs)[RPAD] = (float(*)[RPAD])(smem + VS_OFF);
    float (*Ps)[PPAD] = (float(*)[PPAD])(smem + PS_OFF);
    int* Ms = (int*)(smem + MS_OFF);

    const int qt = blockIdx.x;
    const int h  = blockIdx.y;
    const int b  = blockIdx.z;
    const int g  = h % GROUPS;   // jnp.tile -> head h uses group h % GROUPS
    const int tid = threadIdx.x;
    const int tx = tid & 15;
    const int ty = tid >> 4;

    const int q0 = qt * BQ;
    const float* Qg = g_Q + (size_t)(b * SEQ + q0) * HID + h * HDIM;

    // load Q tile (64 x 128) -> Qs, 8 float4 per thread
#pragma unroll
    for (int u = 0; u < 8; u++) {
        int idf4 = tid + u * 256;      // 0..2047
        int r  = idf4 >> 5;            // 32 float4 per row
        int c4 = idf4 & 31;
        float4 v = *(const float4*)(Qg + (size_t)r * HID + c4 * 4);
        *(float4*)&Qs[r][c4 * 4] = v;
    }

    float m_run[4], l_run[4], o_acc[4][8];
#pragma unroll
    for (int r = 0; r < 4; r++) {
        m_run[r] = -1e30f;
        l_run[r] = 0.f;
#pragma unroll
        for (int c = 0; c < 8; c++) o_acc[r][c] = 0.f;
    }

    const float scale = 0.08838834764831845f;  // 1/sqrt(128)

    for (int kt = 0; kt < SEQ / BK; kt++) {
        const int k0 = kt * BK;
        const float* Kg = g_K + (size_t)(b * SEQ + k0) * KVD + g * HDIM;
        const float* Vg = g_V + (size_t)(b * SEQ + k0) * KVD + g * HDIM;

        __syncthreads();   // previous PV done reading Vs/Ps (also covers first-iter Q visibility)
#pragma unroll
        for (int u = 0; u < 8; u++) {
            int idf4 = tid + u * 256;
            int r  = idf4 >> 5;
            int c4 = idf4 & 31;
            *(float4*)&Ks[r][c4 * 4] = *(const float4*)(Kg + (size_t)r * KVD + c4 * 4);
            *(float4*)&Vs[r][c4 * 4] = *(const float4*)(Vg + (size_t)r * KVD + c4 * 4);
        }
        if (tid < BK) Ms[tid] = mask[b * SEQ + k0 + tid];
        __syncthreads();

        // ---- S = Q @ K^T (each thread: 4x4) ----
        float s_acc[4][4];
#pragma unroll
        for (int r = 0; r < 4; r++)
#pragma unroll
            for (int c = 0; c < 4; c++) s_acc[r][c] = 0.f;

#pragma unroll 2
        for (int d4 = 0; d4 < 32; d4++) {
            float4 qv[4], kv[4];
#pragma unroll
            for (int r = 0; r < 4; r++) qv[r] = *(const float4*)&Qs[ty * 4 + r][d4 * 4];
#pragma unroll
            for (int c = 0; c < 4; c++) kv[c] = *(const float4*)&Ks[tx * 4 + c][d4 * 4];
#pragma unroll
            for (int r = 0; r < 4; r++)
#pragma unroll
                for (int c = 0; c < 4; c++) {
                    s_acc[r][c] += qv[r].x * kv[c].x + qv[r].y * kv[c].y
                                 + qv[r].z * kv[c].z + qv[r].w * kv[c].w;
                }
        }

        // scale + mask
#pragma unroll
        for (int r = 0; r < 4; r++)
#pragma unroll
            for (int c = 0; c < 4; c++) {
                float sv = s_acc[r][c] * scale;
                if (Ms[tx * 4 + c] == 0) sv = -1e30f;
                s_acc[r][c] = sv;
            }

        // ---- online softmax ----
#pragma unroll
        for (int r = 0; r < 4; r++) {
            float tmax = fmaxf(fmaxf(s_acc[r][0], s_acc[r][1]),
                               fmaxf(s_acc[r][2], s_acc[r][3]));
#pragma unroll
            for (int off = 8; off >= 1; off >>= 1)
                tmax = fmaxf(tmax, __shfl_xor_sync(0xffffffffu, tmax, off));

            float m_new = fmaxf(m_run[r], tmax);
            float corr  = __expf(m_run[r] - m_new);
            float psum = 0.f;
#pragma unroll
            for (int c = 0; c < 4; c++) {
                float p = __expf(s_acc[r][c] - m_new);
                s_acc[r][c] = p;
                psum += p;
            }
#pragma unroll
            for (int off = 8; off >= 1; off >>= 1)
                psum += __shfl_xor_sync(0xffffffffu, psum, off);

            l_run[r] = l_run[r] * corr + psum;
            m_run[r] = m_new;
#pragma unroll
            for (int c = 0; c < 8; c++) o_acc[r][c] *= corr;
        }

        // store P to smem for the PV GEMM
#pragma unroll
        for (int r = 0; r < 4; r++) {
            float4 pv = make_float4(s_acc[r][0], s_acc[r][1], s_acc[r][2], s_acc[r][3]);
            *(float4*)&Ps[ty * 4 + r][tx * 4] = pv;
        }
        __syncthreads();

        // ---- O += P @ V (each thread: rows ty*4+r, cols tx*8..+7) ----
#pragma unroll 2
        for (int j = 0; j < BK; j++) {
            float p0 = Ps[ty * 4 + 0][j];
            float p1 = Ps[ty * 4 + 1][j];
            float p2 = Ps[ty * 4 + 2][j];
            float p3 = Ps[ty * 4 + 3][j];
            float4 v0 = *(const float4*)&Vs[j][tx * 8];
            float4 v1 = *(const float4*)&Vs[j][tx * 8 + 4];
            o_acc[0][0] += p0 * v0.x; o_acc[0][1] += p0 * v0.y;
            o_acc[0][2] += p0 * v0.z; o_acc[0][3] += p0 * v0.w;
            o_acc[0][4] += p0 * v1.x; o_acc[0][5] += p0 * v1.y;
            o_acc[0][6] += p0 * v1.z; o_acc[0][7] += p0 * v1.w;
            o_acc[1][0] += p1 * v0.x; o_acc[1][1] += p1 * v0.y;
            o_acc[1][2] += p1 * v0.z; o_acc[1][3] += p1 * v0.w;
            o_acc[1][4] += p1 * v1.x; o_acc[1][5] += p1 * v1.y;
            o_acc[1][6] += p1 * v1.z; o_acc[1][7] += p1 * v1.w;
            o_acc[2][0] += p2 * v0.x; o_acc[2][1] += p2 * v0.y;
            o_acc[2][2] += p2 * v0.z; o_acc[2][3] += p2 * v0.w;
            o_acc[2][4] += p2 * v1.x; o_acc[2][5] += p2 * v1.y;
            o_acc[2][6] += p2 * v1.z; o_acc[2][7] += p2 * v1.w;
            o_acc[3][0] += p3 * v0.x; o_acc[3][1] += p3 * v0.y;
            o_acc[3][2] += p3 * v0.z; o_acc[3][3] += p3 * v0.w;
            o_acc[3][4] += p3 * v1.x; o_acc[3][5] += p3 * v1.y;
            o_acc[3][6] += p3 * v1.z; o_acc[3][7] += p3 * v1.w;
        }
    }

    // epilogue: O /= l, write to g_O
    float* Og = g_O + (size_t)(b * SEQ + q0) * HID + h * HDIM;
#pragma unroll
    for (int r = 0; r < 4; r++) {
        float inv = 1.f / l_run[r];
        float4 o0, o1;
        o0.x = o_acc[r][0] * inv; o0.y = o_acc[r][1] * inv;
        o0.z = o_acc[r][2] * inv; o0.w = o_acc[r][3] * inv;
        o1.x = o_acc[r][4] * inv; o1.y = o_acc[r][5] * inv;
        o1.z = o_acc[r][6] * inv; o1.w = o_acc[r][7] * inv;
        *(float4*)&Og[(size_t)(ty * 4 + r) * HID + tx * 8]     = o0;
        *(float4*)&Og[(size_t)(ty * 4 + r) * HID + tx * 8 + 4] = o1;
    }
}

// ================= launch =================
extern "C" void kernel_launch(void* const* d_in, const int* in_sizes, int n_in,
                              void* d_out, int out_size)
{
    const float* X    = (const float*)d_in[0];
    const int*   mask = (const int*)  d_in[1];
    const float* Wq   = (const float*)d_in[2];
    const float* bq   = (const float*)d_in[3];
    const float* Wk   = (const float*)d_in[4];
    const float* bk   = (const float*)d_in[5];
    const float* Wv   = (const float*)d_in[6];
    const float* bv   = (const float*)d_in[7];
    const float* Wo   = (const float*)d_in[8];
    const float* bo   = (const float*)d_in[9];
    float* out = (float*)d_out;

    float *Qp, *Kp, *Vp, *Op;
    cudaGetSymbolAddress((void**)&Qp, g_Q);
    cudaGetSymbolAddress((void**)&Kp, g_K);
    cudaGetSymbolAddress((void**)&Vp, g_V);
    cudaGetSymbolAddress((void**)&Op, g_O);

    cudaFuncSetAttribute(attn_kernel,
                         cudaFuncAttributeMaxDynamicSharedMemorySize,
                         ATTN_SMEM_BYTES);

    dim3 blk(256);
    // QKV projections
    gemm_bias_kernel<<<dim3(HID / 128, MROWS / 128), blk>>>(X, Wq, bq, Qp, MROWS, HID, HID);
    gemm_bias_kernel<<<dim3(KVD / 128, MROWS / 128), blk>>>(X, Wk, bk, Kp, MROWS, KVD, HID);
    gemm_bias_kernel<<<dim3(KVD / 128, MROWS / 128), blk>>>(X, Wv, bv, Vp, MROWS, KVD, HID);
    // attention
    attn_kernel<<<dim3(SEQ / BQ, HEADS, BATCH), blk, ATTN_SMEM_BYTES>>>(mask);
    // output projection
    gemm_bias_kernel<<<dim3(HID / 128, MROWS / 128), blk>>>(Op, Wo, bo, out, MROWS, HID, HID);
}

// round 4
// speedup vs baseline: 3.3406x; 3.3406x over previous
#include <cuda_runtime.h>
#include <math.h>

#define HID     2048
#define KVD     512
#define HEADS   16
#define GROUPS  4
#define HDIM    128
#define BATCH   2
#define SEQ     2048
#define MROWS   (BATCH*SEQ)   // 4096

// ---------------- scratch (no cudaMalloc allowed) ----------------
__device__ float g_Q[(size_t)MROWS * HID];   // 32 MB
__device__ float g_K[(size_t)MROWS * KVD];   //  8 MB
__device__ float g_V[(size_t)MROWS * KVD];   //  8 MB
__device__ float g_O[(size_t)MROWS * HID];   // 32 MB

// ---------------- helpers ----------------
__device__ __forceinline__ unsigned f2tf(float x) {
    unsigned u;
    asm("cvt.rna.tf32.f32 %0, %1;" : "=r"(u) : "f"(x));
    return u;
}
__device__ __forceinline__ float tfs(float x) {          // tf32-rounded value as float bits
    return __uint_as_float(f2tf(x));
}
__device__ __forceinline__ unsigned uf(float x) { return __float_as_uint(x); }

__device__ __forceinline__ void mma_tf32(float c[4], const unsigned a[4], const unsigned b[2]) {
    asm volatile(
        "mma.sync.aligned.m16n8k8.row.col.f32.tf32.tf32.f32 "
        "{%0,%1,%2,%3},{%4,%5,%6,%7},{%8,%9},{%0,%1,%2,%3};\n"
        : "+f"(c[0]), "+f"(c[1]), "+f"(c[2]), "+f"(c[3])
        : "r"(a[0]), "r"(a[1]), "r"(a[2]), "r"(a[3]), "r"(b[0]), "r"(b[1]));
}

// ================= GEMM (tf32 tensor cores): C[M,N] = A[M,K]@W[K,N] + bias =================
// 128x128x16 tile, 256 threads = 8 warps (4x2), warp tile 32x64.
// As[128][20]: bank(20r+k) conflict-free for A-frag reads.
// Bs[16][136]: bank(8k+n)  conflict-free for B-frag reads.
__global__ __launch_bounds__(256) void gemm_mma(
    const float* __restrict__ A, const float* __restrict__ W,
    const float* __restrict__ bias, float* __restrict__ C,
    int M, int N, int K)
{
    __shared__ float As[2][128][20];
    __shared__ float Bs[2][16][136];

    const int tid = threadIdx.x;
    const int lane = tid & 31, wid = tid >> 5;
    const int gid = lane >> 2, tig = lane & 3;
    const int wm = wid >> 1, wn = wid & 1;
    const int bm = blockIdx.y * 128, bn = blockIdx.x * 128;

    float acc[2][8][4];
#pragma unroll
    for (int i = 0; i < 2; i++)
#pragma unroll
        for (int j = 0; j < 8; j++)
#pragma unroll
            for (int v = 0; v < 4; v++) acc[i][j][v] = 0.f;

    // A tile: 128 rows x 16 cols = 512 float4; thread loads rows ar and ar+64
    const int ar = tid >> 2, ac4 = tid & 3;
    const float* Ap = A + (size_t)(bm + ar) * K + ac4 * 4;
    // B tile: 16 rows x 128 cols = 512 float4; thread loads rows br and br+8
    const int br = tid >> 5, bc4 = tid & 31;
    const float* Bp = W + (size_t)br * N + bn + bc4 * 4;

    const int T = K / 16;

    float4 a0v = *(const float4*)Ap;
    float4 a1v = *(const float4*)(Ap + (size_t)64 * K);
    float4 b0v = *(const float4*)Bp;
    float4 b1v = *(const float4*)(Bp + (size_t)8 * N);

    // store tile 0 into buffer 0
    {
        float* p0 = &As[0][ar][ac4 * 4];
        p0[0] = tfs(a0v.x); p0[1] = tfs(a0v.y); p0[2] = tfs(a0v.z); p0[3] = tfs(a0v.w);
        float* p1 = &As[0][ar + 64][ac4 * 4];
        p1[0] = tfs(a1v.x); p1[1] = tfs(a1v.y); p1[2] = tfs(a1v.z); p1[3] = tfs(a1v.w);
        float4 t0 = make_float4(tfs(b0v.x), tfs(b0v.y), tfs(b0v.z), tfs(b0v.w));
        float4 t1 = make_float4(tfs(b1v.x), tfs(b1v.y), tfs(b1v.z), tfs(b1v.w));
        *(float4*)&Bs[0][br][bc4 * 4] = t0;
        *(float4*)&Bs[0][br + 8][bc4 * 4] = t1;
    }
    __syncthreads();

    int buf = 0;
    for (int t = 0; t < T; t++) {
        if (t + 1 < T) {
            const float* Ap2 = Ap + (size_t)(t + 1) * 16;
            const float* Bp2 = Bp + (size_t)(t + 1) * 16 * N;
            a0v = *(const float4*)Ap2;
            a1v = *(const float4*)(Ap2 + (size_t)64 * K);
            b0v = *(const float4*)Bp2;
            b1v = *(const float4*)(Bp2 + (size_t)8 * N);
        }

#pragma unroll
        for (int kk = 0; kk < 16; kk += 8) {
            unsigned a[2][4];
#pragma unroll
            for (int mt = 0; mt < 2; mt++) {
                int r = wm * 32 + mt * 16 + gid;
                a[mt][0] = uf(As[buf][r][kk + tig]);
                a[mt][1] = uf(As[buf][r + 8][kk + tig]);
                a[mt][2] = uf(As[buf][r][kk + tig + 4]);
                a[mt][3] = uf(As[buf][r + 8][kk + tig + 4]);
            }
#pragma unroll
            for (int nt = 0; nt < 8; nt++) {
                unsigned bf[2];
                int c = wn * 64 + nt * 8 + gid;
                bf[0] = uf(Bs[buf][kk + tig][c]);
                bf[1] = uf(Bs[buf][kk + tig + 4][c]);
                mma_tf32(acc[0][nt], a[0], bf);
                mma_tf32(acc[1][nt], a[1], bf);
            }
        }

        if (t + 1 < T) {
            int nb = buf ^ 1;
            float* p0 = &As[nb][ar][ac4 * 4];
            p0[0] = tfs(a0v.x); p0[1] = tfs(a0v.y); p0[2] = tfs(a0v.z); p0[3] = tfs(a0v.w);
            float* p1 = &As[nb][ar + 64][ac4 * 4];
            p1[0] = tfs(a1v.x); p1[1] = tfs(a1v.y); p1[2] = tfs(a1v.z); p1[3] = tfs(a1v.w);
            float4 t0 = make_float4(tfs(b0v.x), tfs(b0v.y), tfs(b0v.z), tfs(b0v.w));
            float4 t1 = make_float4(tfs(b1v.x), tfs(b1v.y), tfs(b1v.z), tfs(b1v.w));
            *(float4*)&Bs[nb][br][bc4 * 4] = t0;
            *(float4*)&Bs[nb][br + 8][bc4 * 4] = t1;
            __syncthreads();
            buf = nb;
        }
    }

    // epilogue
#pragma unroll
    for (int mt = 0; mt < 2; mt++) {
        int r0 = bm + wm * 32 + mt * 16 + gid;
#pragma unroll
        for (int nt = 0; nt < 8; nt++) {
            int c = bn + wn * 64 + nt * 8 + 2 * tig;
            float bx = bias[c], by = bias[c + 1];
            float2 v0 = make_float2(acc[mt][nt][0] + bx, acc[mt][nt][1] + by);
            float2 v1 = make_float2(acc[mt][nt][2] + bx, acc[mt][nt][3] + by);
            *(float2*)&C[(size_t)r0 * N + c] = v0;
            *(float2*)&C[(size_t)(r0 + 8) * N + c] = v1;
        }
    }
}

// ================= Flash attention on tensor cores =================
// 128 threads = 4 warps. Q tile 64x128 (warp owns 16 rows), K/V tiles 32x128.
#define AQP 132
#define AKP 132
#define AVP 136
#define APP 36
#define OQ_  0
#define OKs  (64*AQP)            // 8448
#define OVs  (OKs + 32*AKP)      // +4224
#define OPs  (OVs + 32*AVP)      // +4352
#define OMs  (OPs + 64*APP)      // +2304
#define ASMEM ((OMs + 32) * 4)

__global__ __launch_bounds__(128) void attn_mma(const int* __restrict__ mask)
{
    extern __shared__ float sm[];
    float (*Qs)[AQP] = (float(*)[AQP])(sm + OQ_);
    float (*Ks)[AKP] = (float(*)[AKP])(sm + OKs);
    float (*Vs)[AVP] = (float(*)[AVP])(sm + OVs);
    float (*Ps)[APP] = (float(*)[APP])(sm + OPs);
    int* Ms = (int*)(sm + OMs);

    const int tid = threadIdx.x;
    const int w = tid >> 5, lane = tid & 31;
    const int gid = lane >> 2, tig = lane & 3;
    const int qt = blockIdx.x, h = blockIdx.y, b = blockIdx.z;
    const int g = h % GROUPS;
    const int q0 = qt * 64;

    const float scale = 0.08838834764831845f;  // 1/sqrt(128)
    const float* Qg = g_Q + (size_t)(b * SEQ + q0) * HID + h * HDIM;

    // load Q tile, pre-scaled + tf32-rounded
#pragma unroll
    for (int u = 0; u < 16; u++) {
        int idx = tid + u * 128;
        int r = idx >> 5, c4 = idx & 31;
        float4 v = *(const float4*)(Qg + (size_t)r * HID + c4 * 4);
        float4 o = make_float4(tfs(v.x * scale), tfs(v.y * scale),
                               tfs(v.z * scale), tfs(v.w * scale));
        *(float4*)&Qs[r][c4 * 4] = o;
    }

    float m_run[2] = {-1e30f, -1e30f};
    float l_run[2] = {0.f, 0.f};
    float o_acc[16][4];
#pragma unroll
    for (int nt = 0; nt < 16; nt++)
#pragma unroll
        for (int v = 0; v < 4; v++) o_acc[nt][v] = 0.f;

    const float* Kg0 = g_K + (size_t)(b * SEQ) * KVD + g * HDIM;
    const float* Vg0 = g_V + (size_t)(b * SEQ) * KVD + g * HDIM;

    for (int kt = 0; kt < SEQ / 32; kt++) {
        const int k0 = kt * 32;
        __syncthreads();   // prev iter done reading Ks/Vs (first iter: Qs visible)
#pragma unroll
        for (int u = 0; u < 8; u++) {
            int idx = tid + u * 128;
            int r = idx >> 5, c4 = idx & 31;
            float4 kv = *(const float4*)(Kg0 + (size_t)(k0 + r) * KVD + c4 * 4);
            float4 vv = *(const float4*)(Vg0 + (size_t)(k0 + r) * KVD + c4 * 4);
            float4 ok = make_float4(tfs(kv.x), tfs(kv.y), tfs(kv.z), tfs(kv.w));
            float4 ov = make_float4(tfs(vv.x), tfs(vv.y), tfs(vv.z), tfs(vv.w));
            *(float4*)&Ks[r][c4 * 4] = ok;
            *(float4*)&Vs[r][c4 * 4] = ov;
        }
        if (tid < 32) Ms[tid] = mask[b * SEQ + k0 + tid];
        __syncthreads();

        // ---- S = Q @ K^T  (warp: 16 rows x 32 keys) ----
        float s[4][4];
#pragma unroll
        for (int nt = 0; nt < 4; nt++)
#pragma unroll
            for (int v = 0; v < 4; v++) s[nt][v] = 0.f;

#pragma unroll
        for (int ks = 0; ks < 16; ks++) {
            const int kk = ks * 8;
            unsigned qa[4];
            const int r = w * 16 + gid;
            qa[0] = uf(Qs[r][kk + tig]);
            qa[1] = uf(Qs[r + 8][kk + tig]);
            qa[2] = uf(Qs[r][kk + tig + 4]);
            qa[3] = uf(Qs[r + 8][kk + tig + 4]);
#pragma unroll
            for (int nt = 0; nt < 4; nt++) {
                unsigned kb[2];
                kb[0] = uf(Ks[nt * 8 + gid][kk + tig]);
                kb[1] = uf(Ks[nt * 8 + gid][kk + tig + 4]);
                mma_tf32(s[nt], qa, kb);
            }
        }

        // ---- mask ----
#pragma unroll
        for (int nt = 0; nt < 4; nt++) {
            int c = nt * 8 + 2 * tig;
            if (Ms[c] == 0)     { s[nt][0] = -1e30f; s[nt][2] = -1e30f; }
            if (Ms[c + 1] == 0) { s[nt][1] = -1e30f; s[nt][3] = -1e30f; }
        }

        // ---- online softmax (two row-halves: gid row and gid+8) ----
#pragma unroll
        for (int hh = 0; hh < 2; hh++) {
            float mx = -1e30f;
#pragma unroll
            for (int nt = 0; nt < 4; nt++)
                mx = fmaxf(mx, fmaxf(s[nt][2 * hh], s[nt][2 * hh + 1]));
            mx = fmaxf(mx, __shfl_xor_sync(0xffffffffu, mx, 1));
            mx = fmaxf(mx, __shfl_xor_sync(0xffffffffu, mx, 2));
            float mnew = fmaxf(m_run[hh], mx);
            float corr = __expf(m_run[hh] - mnew);
            float sum = 0.f;
#pragma unroll
            for (int nt = 0; nt < 4; nt++) {
                float p0 = __expf(s[nt][2 * hh] - mnew);
                float p1 = __expf(s[nt][2 * hh + 1] - mnew);
                s[nt][2 * hh] = p0; s[nt][2 * hh + 1] = p1;
                sum += p0 + p1;
            }
            sum += __shfl_xor_sync(0xffffffffu, sum, 1);
            sum += __shfl_xor_sync(0xffffffffu, sum, 2);
            l_run[hh] = l_run[hh] * corr + sum;
            m_run[hh] = mnew;
#pragma unroll
            for (int nt = 0; nt < 16; nt++) {
                o_acc[nt][2 * hh] *= corr;
                o_acc[nt][2 * hh + 1] *= corr;
            }
        }

        // ---- store P (own warp rows only) ----
#pragma unroll
        for (int nt = 0; nt < 4; nt++) {
            int r = w * 16 + gid, c = nt * 8 + 2 * tig;
            float2 p0 = make_float2(tfs(s[nt][0]), tfs(s[nt][1]));
            float2 p1 = make_float2(tfs(s[nt][2]), tfs(s[nt][3]));
            *(float2*)&Ps[r][c] = p0;
            *(float2*)&Ps[r + 8][c] = p1;
        }
        __syncwarp();

        // ---- O += P @ V  (warp: 16 rows x 128 dims) ----
#pragma unroll
        for (int ks = 0; ks < 4; ks++) {
            const int kk = ks * 8;
            unsigned pa[4];
            const int r = w * 16 + gid;
            pa[0] = uf(Ps[r][kk + tig]);
            pa[1] = uf(Ps[r + 8][kk + tig]);
            pa[2] = uf(Ps[r][kk + tig + 4]);
            pa[3] = uf(Ps[r + 8][kk + tig + 4]);
#pragma unroll
            for (int nt = 0; nt < 16; nt++) {
                unsigned vb[2];
                vb[0] = uf(Vs[kk + tig][nt * 8 + gid]);
                vb[1] = uf(Vs[kk + tig + 4][nt * 8 + gid]);
                mma_tf32(o_acc[nt], pa, vb);
            }
        }
    }

    // ---- epilogue: O /= l ----
    float* Og = g_O + (size_t)(b * SEQ + q0) * HID + h * HDIM;
    const float i0 = 1.f / l_run[0], i1 = 1.f / l_run[1];
#pragma unroll
    for (int nt = 0; nt < 16; nt++) {
        int r = w * 16 + gid, c = nt * 8 + 2 * tig;
        float2 v0 = make_float2(o_acc[nt][0] * i0, o_acc[nt][1] * i0);
        float2 v1 = make_float2(o_acc[nt][2] * i1, o_acc[nt][3] * i1);
        *(float2*)&Og[(size_t)r * HID + c] = v0;
        *(float2*)&Og[(size_t)(r + 8) * HID + c] = v1;
    }
}

// ================= launch =================
extern "C" void kernel_launch(void* const* d_in, const int* in_sizes, int n_in,
                              void* d_out, int out_size)
{
    const float* X    = (const float*)d_in[0];
    const int*   mask = (const int*)  d_in[1];
    const float* Wq   = (const float*)d_in[2];
    const float* bq   = (const float*)d_in[3];
    const float* Wk   = (const float*)d_in[4];
    const float* bk   = (const float*)d_in[5];
    const float* Wv   = (const float*)d_in[6];
    const float* bv   = (const float*)d_in[7];
    const float* Wo   = (const float*)d_in[8];
    const float* bo   = (const float*)d_in[9];
    float* out = (float*)d_out;

    float *Qp, *Kp, *Vp, *Op;
    cudaGetSymbolAddress((void**)&Qp, g_Q);
    cudaGetSymbolAddress((void**)&Kp, g_K);
    cudaGetSymbolAddress((void**)&Vp, g_V);
    cudaGetSymbolAddress((void**)&Op, g_O);

    cudaFuncSetAttribute(attn_mma,
                         cudaFuncAttributeMaxDynamicSharedMemorySize,
                         ASMEM);

    dim3 blk(256);
    gemm_mma<<<dim3(HID / 128, MROWS / 128), blk>>>(X, Wq, bq, Qp, MROWS, HID, HID);
    gemm_mma<<<dim3(KVD / 128, MROWS / 128), blk>>>(X, Wk, bk, Kp, MROWS, KVD, HID);
    gemm_mma<<<dim3(KVD / 128, MROWS / 128), blk>>>(X, Wv, bv, Vp, MROWS, KVD, HID);

    attn_mma<<<dim3(SEQ / 64, HEADS, BATCH), dim3(128), ASMEM>>>(mask);

    gemm_mma<<<dim3(HID / 128, MROWS / 128), blk>>>(Op, Wo, bo, out, MROWS, HID, HID);
}

// round 5
// speedup vs baseline: 4.3579x; 1.3045x over previous
#include <cuda_runtime.h>
#include <math.h>

#define HID     2048
#define KVD     512
#define HEADS   16
#define GROUPS  4
#define HDIM    128
#define BATCH   2
#define SEQ     2048
#define MROWS   (BATCH*SEQ)   // 4096

// ---------------- scratch (no cudaMalloc allowed) ----------------
__device__ float g_Q[(size_t)MROWS * HID];   // 32 MB
__device__ float g_K[(size_t)MROWS * KVD];   //  8 MB
__device__ float g_V[(size_t)MROWS * KVD];   //  8 MB
__device__ float g_O[(size_t)MROWS * HID];   // 32 MB

// ---------------- helpers ----------------
__device__ __forceinline__ unsigned f2tf(float x) {
    unsigned u;
    asm("cvt.rna.tf32.f32 %0, %1;" : "=r"(u) : "f"(x));
    return u;
}
__device__ __forceinline__ float tfs(float x) { return __uint_as_float(f2tf(x)); }
__device__ __forceinline__ unsigned uf(float x) { return __float_as_uint(x); }
__device__ __forceinline__ unsigned uft(float x) { return f2tf(x); }  // cvt + reinterpret

__device__ __forceinline__ void mma_tf32(float c[4], const unsigned a[4], const unsigned b[2]) {
    asm volatile(
        "mma.sync.aligned.m16n8k8.row.col.f32.tf32.tf32.f32 "
        "{%0,%1,%2,%3},{%4,%5,%6,%7},{%8,%9},{%0,%1,%2,%3};\n"
        : "+f"(c[0]), "+f"(c[1]), "+f"(c[2]), "+f"(c[3])
        : "r"(a[0]), "r"(a[1]), "r"(a[2]), "r"(a[3]), "r"(b[0]), "r"(b[1]));
}

__device__ __forceinline__ void cp_async16(void* smem, const void* gmem) {
    unsigned sa = (unsigned)__cvta_generic_to_shared(smem);
    asm volatile("cp.async.cg.shared.global [%0], [%1], 16;\n" :: "r"(sa), "l"(gmem));
}
#define CP_COMMIT asm volatile("cp.async.commit_group;\n")
#define CP_WAIT0  asm volatile("cp.async.wait_group 0;\n")

// ================= GEMM (tf32 tensor cores): C[M,N] = A[M,K]@W[K,N] + bias =================
// 128x128x32 tile, 256 threads = 8 warps (4x2), warp tile 32x64, 2-stage cp.async.
// As[st][128][36]: bank(36r+k) = 4r+k mod 32 -> conflict-free A-frag reads.
// Bs[st][32][136]: bank(136k+n) = 8k+n mod 32 -> conflict-free B-frag reads.
#define GBK 32
#define G_AS (128*36)
#define G_BS (32*136)
#define GSMEM ((2*G_AS + 2*G_BS) * 4)   // 71680 B

__global__ __launch_bounds__(256, 2) void gemm_mma(
    const float* __restrict__ A, const float* __restrict__ W,
    const float* __restrict__ bias, float* __restrict__ C,
    int M, int N, int K)
{
    extern __shared__ float gsm[];
    float (*As)[128][36]  = (float(*)[128][36])gsm;
    float (*Bs)[32][136]  = (float(*)[32][136])(gsm + 2 * G_AS);

    const int tid = threadIdx.x;
    const int lane = tid & 31, wid = tid >> 5;
    const int gid = lane >> 2, tig = lane & 3;
    const int wm = wid >> 1, wn = wid & 1;
    const int bm = blockIdx.y * 128, bn = blockIdx.x * 128;

    float acc[2][8][4];
#pragma unroll
    for (int i = 0; i < 2; i++)
#pragma unroll
        for (int j = 0; j < 8; j++)
#pragma unroll
            for (int v = 0; v < 4; v++) acc[i][j][v] = 0.f;

    const int T = K / GBK;

    // stage loader: A tile 128x32 (1024 16B chunks), B tile 32x128 (1024 chunks)
    auto load_stage = [&](int st, int t) {
        const int k0 = t * GBK;
#pragma unroll
        for (int u = 0; u < 4; u++) {
            int id = tid + u * 256;
            int ra = id >> 3, ca = id & 7;           // A: 8 chunks per row
            cp_async16(&As[st][ra][ca * 4],
                       A + (size_t)(bm + ra) * K + k0 + ca * 4);
            int rb = id >> 5, cb = id & 31;          // B: 32 chunks per row
            cp_async16(&Bs[st][rb][cb * 4],
                       W + (size_t)(k0 + rb) * N + bn + cb * 4);
        }
    };

    load_stage(0, 0);
    CP_COMMIT;

    for (int t = 0; t < T; t++) {
        const int st = t & 1;
        CP_WAIT0;
        __syncthreads();
        if (t + 1 < T) {
            load_stage(st ^ 1, t + 1);
            CP_COMMIT;
        }

#pragma unroll
        for (int kk = 0; kk < GBK; kk += 8) {
            unsigned a[2][4];
#pragma unroll
            for (int mt = 0; mt < 2; mt++) {
                int r = wm * 32 + mt * 16 + gid;
                a[mt][0] = uft(As[st][r][kk + tig]);
                a[mt][1] = uft(As[st][r + 8][kk + tig]);
                a[mt][2] = uft(As[st][r][kk + tig + 4]);
                a[mt][3] = uft(As[st][r + 8][kk + tig + 4]);
            }
#pragma unroll
            for (int nt = 0; nt < 8; nt++) {
                unsigned bf[2];
                int c = wn * 64 + nt * 8 + gid;
                bf[0] = uft(Bs[st][kk + tig][c]);
                bf[1] = uft(Bs[st][kk + tig + 4][c]);
                mma_tf32(acc[0][nt], a[0], bf);
                mma_tf32(acc[1][nt], a[1], bf);
            }
        }
    }

    // epilogue
#pragma unroll
    for (int mt = 0; mt < 2; mt++) {
        int r0 = bm + wm * 32 + mt * 16 + gid;
#pragma unroll
        for (int nt = 0; nt < 8; nt++) {
            int c = bn + wn * 64 + nt * 8 + 2 * tig;
            float bx = bias[c], by = bias[c + 1];
            float2 v0 = make_float2(acc[mt][nt][0] + bx, acc[mt][nt][1] + by);
            float2 v1 = make_float2(acc[mt][nt][2] + bx, acc[mt][nt][3] + by);
            *(float2*)&C[(size_t)r0 * N + c] = v0;
            *(float2*)&C[(size_t)(r0 + 8) * N + c] = v1;
        }
    }
}

// ================= Flash attention on tensor cores =================
// 256 threads = 8 warps. Q tile 128x128 (warp owns 16 rows), K/V tiles 32x128,
// double-buffered via cp.async.
#define AQP 132
#define AKP 132
#define AVP 136
#define APP 36
#define OQ_  0
#define OKs  (128*AQP)                 // 16896
#define OVs  (OKs + 2*32*AKP)          // +8448
#define OPs  (OVs + 2*32*AVP)          // +8704
#define OMs  (OPs + 128*APP)           // +4608
#define ASMEM ((OMs + 2*32) * 4)       // 154880 B

__global__ __launch_bounds__(256, 1) void attn_mma(const int* __restrict__ mask)
{
    extern __shared__ float sm[];
    float (*Qs)[AQP]     = (float(*)[AQP])(sm + OQ_);
    float (*Ks)[32][AKP] = (float(*)[32][AKP])(sm + OKs);
    float (*Vs)[32][AVP] = (float(*)[32][AVP])(sm + OVs);
    float (*Ps)[APP]     = (float(*)[APP])(sm + OPs);
    int (*Ms)[32]        = (int(*)[32])(sm + OMs);

    const int tid = threadIdx.x;
    const int w = tid >> 5, lane = tid & 31;
    const int gid = lane >> 2, tig = lane & 3;
    const int qt = blockIdx.x, h = blockIdx.y, b = blockIdx.z;
    const int g = h % GROUPS;
    const int q0 = qt * 128;

    const float scale = 0.08838834764831845f;  // 1/sqrt(128)
    const float* Qg = g_Q + (size_t)(b * SEQ + q0) * HID + h * HDIM;
    const float* Kg0 = g_K + (size_t)(b * SEQ) * KVD + g * HDIM;
    const float* Vg0 = g_V + (size_t)(b * SEQ) * KVD + g * HDIM;
    const int*   Mg0 = mask + b * SEQ;

    auto issue_kv = [&](int st, int kt) {
        const int k0 = kt * 32;
#pragma unroll
        for (int u = 0; u < 4; u++) {
            int id = tid + u * 256;
            int r = id >> 5, c4 = id & 31;
            cp_async16(&Ks[st][r][c4 * 4], Kg0 + (size_t)(k0 + r) * KVD + c4 * 4);
            cp_async16(&Vs[st][r][c4 * 4], Vg0 + (size_t)(k0 + r) * KVD + c4 * 4);
        }
        if (tid < 8) cp_async16(&Ms[st][tid * 4], Mg0 + k0 + tid * 4);
    };

    // prologue: start kt=0 loads, then fill Q tile (pre-scaled + tf32-rounded)
    issue_kv(0, 0);
    CP_COMMIT;

#pragma unroll
    for (int u = 0; u < 16; u++) {
        int idx = tid + u * 256;
        int r = idx >> 5, c4 = idx & 31;
        float4 v = *(const float4*)(Qg + (size_t)r * HID + c4 * 4);
        float4 o = make_float4(tfs(v.x * scale), tfs(v.y * scale),
                               tfs(v.z * scale), tfs(v.w * scale));
        *(float4*)&Qs[r][c4 * 4] = o;
    }

    float m_run[2] = {-1e30f, -1e30f};
    float l_run[2] = {0.f, 0.f};
    float o_acc[16][4];
#pragma unroll
    for (int nt = 0; nt < 16; nt++)
#pragma unroll
        for (int v = 0; v < 4; v++) o_acc[nt][v] = 0.f;

    const int r = w * 16 + gid;   // warp's base row

    for (int kt = 0; kt < SEQ / 32; kt++) {
        const int st = kt & 1;
        CP_WAIT0;
        __syncthreads();          // kt tile ready; all warps done with kt-1 buffers (and Qs visible)
        if (kt + 1 < SEQ / 32) {
            issue_kv(st ^ 1, kt + 1);
            CP_COMMIT;
        }

        // ---- S = Q @ K^T  (warp: 16 rows x 32 keys) ----
        float s[4][4];
#pragma unroll
        for (int nt = 0; nt < 4; nt++)
#pragma unroll
            for (int v = 0; v < 4; v++) s[nt][v] = 0.f;

#pragma unroll
        for (int ks = 0; ks < 16; ks++) {
            const int kk = ks * 8;
            unsigned qa[4];
            qa[0] = uf(Qs[r][kk + tig]);
            qa[1] = uf(Qs[r + 8][kk + tig]);
            qa[2] = uf(Qs[r][kk + tig + 4]);
            qa[3] = uf(Qs[r + 8][kk + tig + 4]);
#pragma unroll
            for (int nt = 0; nt < 4; nt++) {
                unsigned kb[2];
                kb[0] = uft(Ks[st][nt * 8 + gid][kk + tig]);
                kb[1] = uft(Ks[st][nt * 8 + gid][kk + tig + 4]);
                mma_tf32(s[nt], qa, kb);
            }
        }

        // ---- mask ----
#pragma unroll
        for (int nt = 0; nt < 4; nt++) {
            int c = nt * 8 + 2 * tig;
            if (Ms[st][c] == 0)     { s[nt][0] = -1e30f; s[nt][2] = -1e30f; }
            if (Ms[st][c + 1] == 0) { s[nt][1] = -1e30f; s[nt][3] = -1e30f; }
        }

        // ---- online softmax (row halves: gid and gid+8) ----
#pragma unroll
        for (int hh = 0; hh < 2; hh++) {
            float mx = -1e30f;
#pragma unroll
            for (int nt = 0; nt < 4; nt++)
                mx = fmaxf(mx, fmaxf(s[nt][2 * hh], s[nt][2 * hh + 1]));
            mx = fmaxf(mx, __shfl_xor_sync(0xffffffffu, mx, 1));
            mx = fmaxf(mx, __shfl_xor_sync(0xffffffffu, mx, 2));
            float mnew = fmaxf(m_run[hh], mx);
            float corr = __expf(m_run[hh] - mnew);
            float sum = 0.f;
#pragma unroll
            for (int nt = 0; nt < 4; nt++) {
                float p0 = __expf(s[nt][2 * hh] - mnew);
                float p1 = __expf(s[nt][2 * hh + 1] - mnew);
                s[nt][2 * hh] = p0; s[nt][2 * hh + 1] = p1;
                sum += p0 + p1;
            }
            sum += __shfl_xor_sync(0xffffffffu, sum, 1);
            sum += __shfl_xor_sync(0xffffffffu, sum, 2);
            l_run[hh] = l_run[hh] * corr + sum;
            m_run[hh] = mnew;
#pragma unroll
            for (int nt = 0; nt < 16; nt++) {
                o_acc[nt][2 * hh] *= corr;
                o_acc[nt][2 * hh + 1] *= corr;
            }
        }

        // ---- store P (own warp rows only) ----
#pragma unroll
        for (int nt = 0; nt < 4; nt++) {
            int c = nt * 8 + 2 * tig;
            float2 p0 = make_float2(tfs(s[nt][0]), tfs(s[nt][1]));
            float2 p1 = make_float2(tfs(s[nt][2]), tfs(s[nt][3]));
            *(float2*)&Ps[r][c] = p0;
            *(float2*)&Ps[r + 8][c] = p1;
        }
        __syncwarp();

        // ---- O += P @ V  (warp: 16 rows x 128 dims) ----
#pragma unroll
        for (int ks = 0; ks < 4; ks++) {
            const int kk = ks * 8;
            unsigned pa[4];
            pa[0] = uf(Ps[r][kk + tig]);
            pa[1] = uf(Ps[r + 8][kk + tig]);
            pa[2] = uf(Ps[r][kk + tig + 4]);
            pa[3] = uf(Ps[r + 8][kk + tig + 4]);
#pragma unroll
            for (int nt = 0; nt < 16; nt++) {
                unsigned vb[2];
                vb[0] = uft(Vs[st][kk + tig][nt * 8 + gid]);
                vb[1] = uft(Vs[st][kk + tig + 4][nt * 8 + gid]);
                mma_tf32(o_acc[nt], pa, vb);
            }
        }
    }

    // ---- epilogue: O /= l ----
    float* Og = g_O + (size_t)(b * SEQ + q0) * HID + h * HDIM;
    const float i0 = 1.f / l_run[0], i1 = 1.f / l_run[1];
#pragma unroll
    for (int nt = 0; nt < 16; nt++) {
        int c = nt * 8 + 2 * tig;
        float2 v0 = make_float2(o_acc[nt][0] * i0, o_acc[nt][1] * i0);
        float2 v1 = make_float2(o_acc[nt][2] * i1, o_acc[nt][3] * i1);
        *(float2*)&Og[(size_t)r * HID + c] = v0;
        *(float2*)&Og[(size_t)(r + 8) * HID + c] = v1;
    }
}

// ================= launch =================
extern "C" void kernel_launch(void* const* d_in, const int* in_sizes, int n_in,
                              void* d_out, int out_size)
{
    const float* X    = (const float*)d_in[0];
    const int*   mask = (const int*)  d_in[1];
    const float* Wq   = (const float*)d_in[2];
    const float* bq   = (const float*)d_in[3];
    const float* Wk   = (const float*)d_in[4];
    const float* bk   = (const float*)d_in[5];
    const float* Wv   = (const float*)d_in[6];
    const float* bv   = (const float*)d_in[7];
    const float* Wo   = (const float*)d_in[8];
    const float* bo   = (const float*)d_in[9];
    float* out = (float*)d_out;

    float *Qp, *Kp, *Vp, *Op;
    cudaGetSymbolAddress((void**)&Qp, g_Q);
    cudaGetSymbolAddress((void**)&Kp, g_K);
    cudaGetSymbolAddress((void**)&Vp, g_V);
    cudaGetSymbolAddress((void**)&Op, g_O);

    cudaFuncSetAttribute(gemm_mma,
                         cudaFuncAttributeMaxDynamicSharedMemorySize, GSMEM);
    cudaFuncSetAttribute(attn_mma,
                         cudaFuncAttributeMaxDynamicSharedMemorySize, ASMEM);

    dim3 blk(256);
    gemm_mma<<<dim3(HID / 128, MROWS / 128), blk, GSMEM>>>(X, Wq, bq, Qp, MROWS, HID, HID);
    gemm_mma<<<dim3(KVD / 128, MROWS / 128), blk, GSMEM>>>(X, Wk, bk, Kp, MROWS, KVD, HID);
    gemm_mma<<<dim3(KVD / 128, MROWS / 128), blk, GSMEM>>>(X, Wv, bv, Vp, MROWS, KVD, HID);

    attn_mma<<<dim3(SEQ / 128, HEADS, BATCH), blk, ASMEM>>>(mask);

    gemm_mma<<<dim3(HID / 128, MROWS / 128), blk, GSMEM>>>(Op, Wo, bo, out, MROWS, HID, HID);
}